// round 15
// baseline (speedup 1.0000x reference)
#include <cuda_runtime.h>
#include <cuda_fp16.h>
#include <cstdint>

// ============================================================================
// X[16,4096,256] -> proj(256->128)+bp -> relu(W1+b1) -> W2+b2 = Y
// out[b,n,:] = sum_m Y[b,m,:] - Y[b,n,:]
// R14 base (59.5us): 512 CTAs x 256 thr, 4 x 32KB weight sync-regions,
// X f32 cp.async (stride 544), H fp16@272 ldmatrix path.
// R15 delta: Y stored fp16 in scratch (halves Y-store bytes; subtract reads
// fp16 from L2 and writes f32 out once, instead of in-place f32 RMW).
// ============================================================================

__device__ __align__(16) uint32_t g_wpack[8 * 4096];   // packed fp16 weights (128KB)
__device__ __align__(16) uint32_t g_y[65536 * 64];     // Y fp16x2 [row][64] (16.8MB)
__device__ float g_part[512 * 128];

// ---------------- helpers ----------------
__device__ __forceinline__ uint32_t smem_u32(const void* p) {
    uint32_t a;
    asm("{ .reg .u64 t; cvta.to.shared.u64 t, %1; cvt.u32.u64 %0, t; }" : "=r"(a) : "l"(p));
    return a;
}
__device__ __forceinline__ void lds64f(uint32_t a, float& x, float& y) {
    asm volatile("ld.shared.v2.f32 {%0,%1}, [%2];" : "=f"(x), "=f"(y) : "r"(a));
}
__device__ __forceinline__ void lds128u(uint32_t a, uint32_t& x, uint32_t& y, uint32_t& z, uint32_t& w) {
    asm volatile("ld.shared.v4.b32 {%0,%1,%2,%3}, [%4];" : "=r"(x), "=r"(y), "=r"(z), "=r"(w) : "r"(a));
}
__device__ __forceinline__ void sts32u(uint32_t a, uint32_t v) {
    asm volatile("st.shared.b32 [%0], %1;" :: "r"(a), "r"(v));
}
__device__ __forceinline__ uint32_t packh2(float lo, float hi) {
    uint32_t u;
    asm("cvt.rn.f16x2.f32 %0, %1, %2;" : "=r"(u) : "f"(hi), "f"(lo));
    return u;
}
__device__ __forceinline__ void ldmA4(uint32_t a, uint32_t* r) {
    asm volatile("ldmatrix.sync.aligned.m8n8.x4.shared.b16 {%0,%1,%2,%3}, [%4];"
        : "=r"(r[0]), "=r"(r[1]), "=r"(r[2]), "=r"(r[3]) : "r"(a));
}
__device__ __forceinline__ void mma16(float* d,
                                      uint32_t a0, uint32_t a1, uint32_t a2, uint32_t a3,
                                      uint32_t b0, uint32_t b1) {
    asm volatile(
        "mma.sync.aligned.m16n8k16.row.col.f32.f16.f16.f32 "
        "{%0,%1,%2,%3}, {%4,%5,%6,%7}, {%8,%9}, {%0,%1,%2,%3};"
        : "+f"(d[0]), "+f"(d[1]), "+f"(d[2]), "+f"(d[3])
        : "r"(a0), "r"(a1), "r"(a2), "r"(a3), "r"(b0), "r"(b1));
}
#define CP16(dst, src)  asm volatile("cp.async.cg.shared.global [%0], [%1], 16;" :: "r"(dst), "l"(src))
#define CP_COMMIT()     asm volatile("cp.async.commit_group;" ::: "memory")
#define CP_WAIT(n)      asm volatile("cp.async.wait_group %0;" :: "n"(n) : "memory")

// ============================================================================
// prep: pack weights (fp16) into lane-ordered quad layout (proven R4-R14).
// ============================================================================
__global__ void prep_kernel(const float* __restrict__ Wp,
                            const float* __restrict__ W1,
                            const float* __restrict__ W2) {
    int i = blockIdx.x * 256 + threadIdx.x;          // 32768 total
    int chunk = i >> 12;
    int within = i & 4095;
    int q = within & 3, ln = (within >> 2) & 31, bpks = within >> 7;
    int bpi = bpks & 7, ks = bpks >> 3;
    int kl = ks * 16 + (q & 1) * 8 + (ln & 3) * 2;
    int n = bpi * 16 + (q >> 1) * 8 + (ln >> 2);
    const float* W;
    int krow;
    if (chunk < 4)      { W = Wp; krow = chunk * 64 + kl; }
    else if (chunk < 6) { W = W1; krow = (chunk - 4) * 64 + kl; }
    else                { W = W2; krow = (chunk - 6) * 64 + kl; }
    float w0 = W[(size_t)krow * 128 + n];
    float w1 = W[(size_t)(krow + 1) * 128 + n];
    g_wpack[i] = packh2(w0, w1);
}

// ============================================================================
// fused kernel — ~204KB SMEM, 256 threads (8 warps), occ 1, no reg cap.
// ============================================================================
#define SM_A0   0                     // 128*544 = 69632 (Xh0 f32 / H1 fp16@272)
#define SM_A1   69632                 // (Xh1 f32 / H2 fp16@272)
#define SM_W0   139264                // 32KB weight buffer 0
#define SM_W1B  172032                // 32KB weight buffer 1
#define SM_BIAS 204800                // bp[128], b1[128], b2[128] (f32)
#define SM_RED  206336                // 4*128 floats
#define SMEM_SZ 208384

// 32KB chunk = 8 k-steps of 16. f32 A-path (GEMM1): stride 544, LDS.64+cvt.
__device__ __forceinline__ void gemm_chunk_f32(uint32_t aa0, uint32_t wb,
                                               int nh, int l, float acc[2][8][4]) {
    #pragma unroll
    for (int ks = 0; ks < 8; ++ks) {
        uint32_t A[2][4];
        uint32_t ab = aa0 + (uint32_t)ks * 64;
        #pragma unroll
        for (int mb = 0; mb < 2; ++mb) {
            uint32_t p = ab + (uint32_t)mb * (16 * 544);
            float x0, x1, y0, y1, z0, z1, u0, u1;
            lds64f(p, x0, x1);
            lds64f(p + 8 * 544, y0, y1);
            lds64f(p + 32, z0, z1);
            lds64f(p + 8 * 544 + 32, u0, u1);
            A[mb][0] = packh2(x0, x1);
            A[mb][1] = packh2(y0, y1);
            A[mb][2] = packh2(z0, z1);
            A[mb][3] = packh2(u0, u1);
        }
        uint32_t bb = wb + (uint32_t)((ks >> 2) * 16384 + (ks & 3) * 4096)
                         + (uint32_t)(nh * 4) * 512 + (uint32_t)l * 16;
        #pragma unroll
        for (int bpi = 0; bpi < 4; ++bpi) {
            uint32_t q0, q1, q2, q3;
            lds128u(bb + (uint32_t)bpi * 512, q0, q1, q2, q3);
            mma16(acc[0][2 * bpi],     A[0][0], A[0][1], A[0][2], A[0][3], q0, q1);
            mma16(acc[1][2 * bpi],     A[1][0], A[1][1], A[1][2], A[1][3], q0, q1);
            mma16(acc[0][2 * bpi + 1], A[0][0], A[0][1], A[0][2], A[0][3], q2, q3);
            mma16(acc[1][2 * bpi + 1], A[1][0], A[1][1], A[1][2], A[1][3], q2, q3);
        }
    }
}

// 32KB chunk, fp16 ldmatrix A-path (GEMM2/3): H stride 272.
__device__ __forceinline__ void gemm_chunk_h16(uint32_t a_lane, uint32_t wb,
                                               int nh, int l, float acc[2][8][4]) {
    #pragma unroll
    for (int ks = 0; ks < 8; ++ks) {
        uint32_t A0[4], A1[4];
        uint32_t aa = a_lane + (uint32_t)ks * 32;
        ldmA4(aa, A0);
        ldmA4(aa + 16 * 272, A1);
        uint32_t bb = wb + (uint32_t)((ks >> 2) * 16384 + (ks & 3) * 4096)
                         + (uint32_t)(nh * 4) * 512 + (uint32_t)l * 16;
        #pragma unroll
        for (int bpi = 0; bpi < 4; ++bpi) {
            uint32_t q0, q1, q2, q3;
            lds128u(bb + (uint32_t)bpi * 512, q0, q1, q2, q3);
            mma16(acc[0][2 * bpi],     A0[0], A0[1], A0[2], A0[3], q0, q1);
            mma16(acc[1][2 * bpi],     A1[0], A1[1], A1[2], A1[3], q0, q1);
            mma16(acc[0][2 * bpi + 1], A0[0], A0[1], A0[2], A0[3], q2, q3);
            mma16(acc[1][2 * bpi + 1], A1[0], A1[1], A1[2], A1[3], q2, q3);
        }
    }
}

__global__ void __launch_bounds__(256, 1) fused_kernel(
    const float* __restrict__ X,
    const float* __restrict__ bp,
    const float* __restrict__ b1,
    const float* __restrict__ b2)
{
    extern __shared__ char smem[];
    const uint32_t sb = smem_u32(smem);
    const int tid = threadIdx.x;
    const int l = tid & 31;
    const int w = tid >> 5;
    const int wrow = (w >> 1) * 32;        // row group (32 rows per warp)
    const int nh = w & 1;                  // n-half
    const int t = blockIdx.x;

    // prologue: group0 = Xh0->A0 + Wp0->WB0 ; group1 = Xh1->A1 + Wp1->WB1
    const float* xbase = X + (size_t)t * 128 * 256;
    #pragma unroll
    for (int h = 0; h < 2; ++h) {
        uint32_t adst = sb + (h ? SM_A1 : SM_A0);
        for (int i = tid; i < 4096; i += 256) {
            int r = i >> 5, c16 = i & 31;
            CP16(adst + r * 544 + c16 * 16,
                 xbase + (size_t)r * 256 + h * 128 + c16 * 4);
        }
        uint32_t bdst = sb + (h ? SM_W1B : SM_W0);
        const uint4* ws = (const uint4*)(g_wpack + h * 8192);
        for (int i = tid; i < 2048; i += 256) CP16(bdst + i * 16, ws + i);
        CP_COMMIT();
    }
    if (tid < 128) {
        ((float*)(smem + SM_BIAS))[tid]       = bp[tid];
        ((float*)(smem + SM_BIAS))[128 + tid] = b1[tid];
        ((float*)(smem + SM_BIAS))[256 + tid] = b2[tid];
    }

    float acc[2][8][4];
    #pragma unroll
    for (int m = 0; m < 2; ++m)
        #pragma unroll
        for (int nb = 0; nb < 8; ++nb)
            #pragma unroll
            for (int k = 0; k < 4; ++k) acc[m][nb][k] = 0.f;

    const uint32_t f32row = ((uint32_t)wrow + (uint32_t)(l >> 2)) * 544 + (uint32_t)(l & 3) * 8;
    const uint32_t lmrow = ((uint32_t)wrow + (uint32_t)(l & 15)) * 272 + (uint32_t)(l >> 4) * 16;
    const uint32_t aH1 = sb + SM_A0 + lmrow;
    const uint32_t aH2 = sb + SM_A1 + lmrow;

    for (int ch = 0; ch < 4; ++ch) {
        if (ch < 3) { CP_WAIT(1); } else { CP_WAIT(0); }
        __syncthreads();   // chunk ch ready; prev-chunk reads done

        const uint32_t wb = sb + ((ch & 1) ? SM_W1B : SM_W0);
        if (ch == 0)      gemm_chunk_f32(sb + SM_A0 + f32row, wb, nh, l, acc);
        else if (ch == 1) gemm_chunk_f32(sb + SM_A1 + f32row, wb, nh, l, acc);
        else if (ch == 2) gemm_chunk_h16(aH1, wb, nh, l, acc);
        else              gemm_chunk_h16(aH2, wb, nh, l, acc);

        if (ch == 1 || ch == 2) {
            // epi1 (ch1): H1 = acc+bp -> A0 (fp16@272); epi2 (ch2): H2=relu -> A1
            const uint32_t dst = (ch == 1) ? (sb + SM_A0) : (sb + SM_A1);
            const uint32_t bo  = sb + SM_BIAS + (ch == 1 ? 0 : 512) + (uint32_t)nh * 256;
            const bool dorelu = (ch == 2);
            #pragma unroll
            for (int nb = 0; nb < 8; ++nb) {
                float bx, by;
                lds64f(bo + (uint32_t)(nb * 8 + (l & 3) * 2) * 4, bx, by);
                #pragma unroll
                for (int mb = 0; mb < 2; ++mb) {
                    float v0 = acc[mb][nb][0] + bx, v1 = acc[mb][nb][1] + by;
                    float v2 = acc[mb][nb][2] + bx, v3 = acc[mb][nb][3] + by;
                    if (dorelu) {
                        v0 = fmaxf(v0, 0.f); v1 = fmaxf(v1, 0.f);
                        v2 = fmaxf(v2, 0.f); v3 = fmaxf(v3, 0.f);
                    }
                    uint32_t sa = dst + (uint32_t)(wrow + mb * 16 + (l >> 2)) * 272
                                      + (uint32_t)(nh * 64 + nb * 8 + (l & 3) * 2) * 2;
                    sts32u(sa, packh2(v0, v1));
                    sts32u(sa + 8 * 272, packh2(v2, v3));
                    acc[mb][nb][0] = 0.f; acc[mb][nb][1] = 0.f;
                    acc[mb][nb][2] = 0.f; acc[mb][nb][3] = 0.f;
                }
            }
        } else if (ch == 3) {
            // final epilogue: Y (fp16x2) -> g_y, fused per-tile column sums (f32)
            const size_t rb = (size_t)t * 128 + wrow + (l >> 2);
            float cs[8][2];
            #pragma unroll
            for (int nb = 0; nb < 8; ++nb) { cs[nb][0] = 0.f; cs[nb][1] = 0.f; }
            #pragma unroll
            for (int nb = 0; nb < 8; ++nb) {
                float bx, by;
                lds64f(sb + SM_BIAS + 1024 + (uint32_t)(nh * 64 + nb * 8 + (l & 3) * 2) * 4, bx, by);
                const uint32_t cpair = (uint32_t)(nh * 64 + nb * 8 + (l & 3) * 2) >> 1;
                #pragma unroll
                for (int mb = 0; mb < 2; ++mb) {
                    float v0 = acc[mb][nb][0] + bx, v1 = acc[mb][nb][1] + by;
                    float v2 = acc[mb][nb][2] + bx, v3 = acc[mb][nb][3] + by;
                    size_t r0 = (rb + mb * 16) * 64 + cpair;
                    g_y[r0]           = packh2(v0, v1);
                    g_y[r0 + 8 * 64]  = packh2(v2, v3);
                    cs[nb][0] += v0 + v2;
                    cs[nb][1] += v1 + v3;
                }
            }
            #pragma unroll
            for (int nb = 0; nb < 8; ++nb) {
                #pragma unroll
                for (int j = 0; j < 2; ++j) {
                    float s = cs[nb][j];
                    s += __shfl_down_sync(0xFFFFFFFFu, s, 16);
                    s += __shfl_down_sync(0xFFFFFFFFu, s, 8);
                    s += __shfl_down_sync(0xFFFFFFFFu, s, 4);
                    if (l < 4)
                        ((float*)(smem + SM_RED))[(w >> 1) * 128 + nh * 64 + nb * 8 + l * 2 + j] = s;
                }
            }
        }

        __syncthreads();   // weight-buffer reuse + H visibility

        if (ch < 2) {      // prefetch W1 (after ch0) / W2 (after ch1)
            const uint4* ws = (const uint4*)(g_wpack + (ch + 2) * 8192);
            uint32_t bdst = sb + ((ch & 1) ? SM_W1B : SM_W0);
            for (int i = tid; i < 2048; i += 256) CP16(bdst + i * 16, ws + i);
            CP_COMMIT();
        }
    }

    // fold 4 row-groups -> g_part[t][128]
    if (tid < 128) {
        const float* R = (const float*)(smem + SM_RED);
        g_part[(size_t)t * 128 + tid] = R[tid] + R[128 + tid] + R[256 + tid] + R[384 + tid];
    }
}

// ---------------- out = S - Y(fp16)  (f32 out written once) ----------------
__global__ void subtract_kernel(float* __restrict__ out) {
    __shared__ float4 S4[32];
    int b = blockIdx.x, nc = blockIdx.y, tid = threadIdx.x;
    if (tid < 128) {
        float s = 0.f;
        const float* gp = g_part + (size_t)b * 32 * 128 + tid;
        #pragma unroll
        for (int c = 0; c < 32; ++c) s += gp[c * 128];
        ((float*)S4)[tid] = s;
    }
    __syncthreads();
    const size_t rowbase = (size_t)b * 4096 + (size_t)nc * 128;
    const uint2* y2 = (const uint2*)(g_y + rowbase * 64);
    float4* p = (float4*)(out + rowbase * 128);
    for (int i = tid; i < 4096; i += 256) {
        float4 s = S4[i & 31];
        uint2 yv = y2[i];
        __half2 h0 = *reinterpret_cast<const __half2*>(&yv.x);
        __half2 h1 = *reinterpret_cast<const __half2*>(&yv.y);
        float2 f0 = __half22float2(h0);
        float2 f1 = __half22float2(h1);
        p[i] = make_float4(s.x - f0.x, s.y - f0.y, s.z - f1.x, s.w - f1.y);
    }
}

// ---------------- launch ----------------
extern "C" void kernel_launch(void* const* d_in, const int* in_sizes, int n_in,
                              void* d_out, int out_size) {
    const float* X  = (const float*)d_in[0];
    const float* Wp = (const float*)d_in[1];
    const float* bp = (const float*)d_in[2];
    const float* W1 = (const float*)d_in[3];
    const float* b1 = (const float*)d_in[4];
    const float* W2 = (const float*)d_in[5];
    const float* b2 = (const float*)d_in[6];
    float* out = (float*)d_out;

    cudaFuncSetAttribute(fused_kernel,
                         cudaFuncAttributeMaxDynamicSharedMemorySize, SMEM_SZ);

    prep_kernel<<<128, 256>>>(Wp, W1, W2);
    fused_kernel<<<512, 256, SMEM_SZ>>>(X, bp, b1, b2);
    subtract_kernel<<<dim3(16, 32), 256>>>(out);
}

// round 16
// speedup vs baseline: 1.0697x; 1.0697x over previous
#include <cuda_runtime.h>
#include <cuda_fp16.h>
#include <cstdint>

// ============================================================================
// X[16,4096,256] -> proj(256->128)+bp -> relu(W1+b1) -> W2+b2 = Y
// out[b,n,:] = sum_m Y[b,m,:] - Y[b,n,:]
// R14 base (59.5us best): 512 CTAs x 256 thr, 4 x 32KB weight chunks,
// X f32 cp.async (stride 544), H fp16@272 ldmatrix path, f32 out, fused
// column sums. R16 delta: barrier restructure — 3 __syncthreads + 1
// 64-thread pair-barrier per tile (was 8 __syncthreads). W1/W2 prefetched
// into both buffers during ch0/ch1 so the back half needs no reuse barrier.
// ============================================================================

__device__ __align__(16) uint32_t g_wpack[8 * 4096];  // packed fp16 weights (128KB)
__device__ float g_part[512 * 128];

// ---------------- helpers ----------------
__device__ __forceinline__ uint32_t smem_u32(const void* p) {
    uint32_t a;
    asm("{ .reg .u64 t; cvta.to.shared.u64 t, %1; cvt.u32.u64 %0, t; }" : "=r"(a) : "l"(p));
    return a;
}
__device__ __forceinline__ void lds64f(uint32_t a, float& x, float& y) {
    asm volatile("ld.shared.v2.f32 {%0,%1}, [%2];" : "=f"(x), "=f"(y) : "r"(a));
}
__device__ __forceinline__ void lds128u(uint32_t a, uint32_t& x, uint32_t& y, uint32_t& z, uint32_t& w) {
    asm volatile("ld.shared.v4.b32 {%0,%1,%2,%3}, [%4];" : "=r"(x), "=r"(y), "=r"(z), "=r"(w) : "r"(a));
}
__device__ __forceinline__ void sts32u(uint32_t a, uint32_t v) {
    asm volatile("st.shared.b32 [%0], %1;" :: "r"(a), "r"(v));
}
__device__ __forceinline__ uint32_t packh2(float lo, float hi) {
    uint32_t u;
    asm("cvt.rn.f16x2.f32 %0, %1, %2;" : "=r"(u) : "f"(hi), "f"(lo));
    return u;
}
__device__ __forceinline__ void ldmA4(uint32_t a, uint32_t* r) {
    asm volatile("ldmatrix.sync.aligned.m8n8.x4.shared.b16 {%0,%1,%2,%3}, [%4];"
        : "=r"(r[0]), "=r"(r[1]), "=r"(r[2]), "=r"(r[3]) : "r"(a));
}
__device__ __forceinline__ void mma16(float* d,
                                      uint32_t a0, uint32_t a1, uint32_t a2, uint32_t a3,
                                      uint32_t b0, uint32_t b1) {
    asm volatile(
        "mma.sync.aligned.m16n8k16.row.col.f32.f16.f16.f32 "
        "{%0,%1,%2,%3}, {%4,%5,%6,%7}, {%8,%9}, {%0,%1,%2,%3};"
        : "+f"(d[0]), "+f"(d[1]), "+f"(d[2]), "+f"(d[3])
        : "r"(a0), "r"(a1), "r"(a2), "r"(a3), "r"(b0), "r"(b1));
}
#define CP16(dst, src)  asm volatile("cp.async.cg.shared.global [%0], [%1], 16;" :: "r"(dst), "l"(src))
#define CP_COMMIT()     asm volatile("cp.async.commit_group;" ::: "memory")
#define CP_WAIT(n)      asm volatile("cp.async.wait_group %0;" :: "n"(n) : "memory")
#define BAR64(id)       asm volatile("bar.sync %0, 64;" :: "r"(id) : "memory")

// ============================================================================
// prep: pack weights (fp16) into lane-ordered quad layout (proven R4-R15).
// 16KB sub-chunk c (0..7) covers 64 k-rows x 128 n (0-3:Wp, 4-5:W1, 6-7:W2).
// uint32 idx within sub-chunk: ((ks*8+bp)*32 + lane)*4 + q, where
//   k_local = ks*16 + (q&1)*8 + (lane&3)*2 ; n = bp*16 + (q>>1)*8 + (lane>>2)
// ============================================================================
__global__ void prep_kernel(const float* __restrict__ Wp,
                            const float* __restrict__ W1,
                            const float* __restrict__ W2) {
    int i = blockIdx.x * 256 + threadIdx.x;          // 32768 total
    int chunk = i >> 12;
    int within = i & 4095;
    int q = within & 3, ln = (within >> 2) & 31, bpks = within >> 7;
    int bpi = bpks & 7, ks = bpks >> 3;
    int kl = ks * 16 + (q & 1) * 8 + (ln & 3) * 2;
    int n = bpi * 16 + (q >> 1) * 8 + (ln >> 2);
    const float* W;
    int krow;
    if (chunk < 4)      { W = Wp; krow = chunk * 64 + kl; }
    else if (chunk < 6) { W = W1; krow = (chunk - 4) * 64 + kl; }
    else                { W = W2; krow = (chunk - 6) * 64 + kl; }
    float w0 = W[(size_t)krow * 128 + n];
    float w1 = W[(size_t)(krow + 1) * 128 + n];
    g_wpack[i] = packh2(w0, w1);
}

// ============================================================================
// fused kernel — ~204KB SMEM, 256 threads (8 warps), occ 1, no reg cap.
// ============================================================================
#define SM_A0   0                     // 128*544 = 69632 (Xh0 f32 / H1 fp16@272)
#define SM_A1   69632                 // (Xh1 f32 / H2 fp16@272)
#define SM_W0   139264                // 32KB weight buffer 0
#define SM_W1B  172032                // 32KB weight buffer 1
#define SM_BIAS 204800                // bp[128], b1[128], b2[128] (f32)
#define SM_RED  206336                // 4*128 floats
#define SMEM_SZ 208384

// 32KB chunk = 8 k-steps of 16. f32 A-path (GEMM1): stride 544, LDS.64+cvt.
__device__ __forceinline__ void gemm_chunk_f32(uint32_t aa0, uint32_t wb,
                                               int nh, int l, float acc[2][8][4]) {
    #pragma unroll
    for (int ks = 0; ks < 8; ++ks) {
        uint32_t A[2][4];
        uint32_t ab = aa0 + (uint32_t)ks * 64;
        #pragma unroll
        for (int mb = 0; mb < 2; ++mb) {
            uint32_t p = ab + (uint32_t)mb * (16 * 544);
            float x0, x1, y0, y1, z0, z1, u0, u1;
            lds64f(p, x0, x1);
            lds64f(p + 8 * 544, y0, y1);
            lds64f(p + 32, z0, z1);
            lds64f(p + 8 * 544 + 32, u0, u1);
            A[mb][0] = packh2(x0, x1);
            A[mb][1] = packh2(y0, y1);
            A[mb][2] = packh2(z0, z1);
            A[mb][3] = packh2(u0, u1);
        }
        uint32_t bb = wb + (uint32_t)((ks >> 2) * 16384 + (ks & 3) * 4096)
                         + (uint32_t)(nh * 4) * 512 + (uint32_t)l * 16;
        #pragma unroll
        for (int bpi = 0; bpi < 4; ++bpi) {
            uint32_t q0, q1, q2, q3;
            lds128u(bb + (uint32_t)bpi * 512, q0, q1, q2, q3);
            mma16(acc[0][2 * bpi],     A[0][0], A[0][1], A[0][2], A[0][3], q0, q1);
            mma16(acc[1][2 * bpi],     A[1][0], A[1][1], A[1][2], A[1][3], q0, q1);
            mma16(acc[0][2 * bpi + 1], A[0][0], A[0][1], A[0][2], A[0][3], q2, q3);
            mma16(acc[1][2 * bpi + 1], A[1][0], A[1][1], A[1][2], A[1][3], q2, q3);
        }
    }
}

// 32KB chunk, fp16 ldmatrix A-path (GEMM2/3): H stride 272.
__device__ __forceinline__ void gemm_chunk_h16(uint32_t a_lane, uint32_t wb,
                                               int nh, int l, float acc[2][8][4]) {
    #pragma unroll
    for (int ks = 0; ks < 8; ++ks) {
        uint32_t A0[4], A1[4];
        uint32_t aa = a_lane + (uint32_t)ks * 32;
        ldmA4(aa, A0);
        ldmA4(aa + 16 * 272, A1);
        uint32_t bb = wb + (uint32_t)((ks >> 2) * 16384 + (ks & 3) * 4096)
                         + (uint32_t)(nh * 4) * 512 + (uint32_t)l * 16;
        #pragma unroll
        for (int bpi = 0; bpi < 4; ++bpi) {
            uint32_t q0, q1, q2, q3;
            lds128u(bb + (uint32_t)bpi * 512, q0, q1, q2, q3);
            mma16(acc[0][2 * bpi],     A0[0], A0[1], A0[2], A0[3], q0, q1);
            mma16(acc[1][2 * bpi],     A1[0], A1[1], A1[2], A1[3], q0, q1);
            mma16(acc[0][2 * bpi + 1], A0[0], A0[1], A0[2], A0[3], q2, q3);
            mma16(acc[1][2 * bpi + 1], A1[0], A1[1], A1[2], A1[3], q2, q3);
        }
    }
}

__global__ void __launch_bounds__(256, 1) fused_kernel(
    const float* __restrict__ X,
    const float* __restrict__ bp,
    const float* __restrict__ b1,
    const float* __restrict__ b2,
    float* __restrict__ out)
{
    extern __shared__ char smem[];
    const uint32_t sb = smem_u32(smem);
    const int tid = threadIdx.x;
    const int l = tid & 31;
    const int w = tid >> 5;
    const int wrow = (w >> 1) * 32;        // row group (32 rows per warp)
    const int nh = w & 1;                  // n-half
    const int t = blockIdx.x;

    // prologue: g0 = {Xh0->A0, Wp0->W0buf} ; g1 = {Xh1->A1, Wp1->W1buf}
    const float* xbase = X + (size_t)t * 128 * 256;
    #pragma unroll
    for (int h = 0; h < 2; ++h) {
        uint32_t adst = sb + (h ? SM_A1 : SM_A0);
        for (int i = tid; i < 4096; i += 256) {
            int r = i >> 5, c16 = i & 31;
            CP16(adst + r * 544 + c16 * 16,
                 xbase + (size_t)r * 256 + h * 128 + c16 * 4);
        }
        uint32_t bdst = sb + (h ? SM_W1B : SM_W0);
        const uint4* ws = (const uint4*)(g_wpack + h * 8192);
        for (int i = tid; i < 2048; i += 256) CP16(bdst + i * 16, ws + i);
        CP_COMMIT();
    }
    if (tid < 128) {
        ((float*)(smem + SM_BIAS))[tid]       = bp[tid];
        ((float*)(smem + SM_BIAS))[128 + tid] = b1[tid];
        ((float*)(smem + SM_BIAS))[256 + tid] = b2[tid];
    }

    float acc[2][8][4];
    #pragma unroll
    for (int m = 0; m < 2; ++m)
        #pragma unroll
        for (int nb = 0; nb < 8; ++nb)
            #pragma unroll
            for (int k = 0; k < 4; ++k) acc[m][nb][k] = 0.f;

    const uint32_t f32row = ((uint32_t)wrow + (uint32_t)(l >> 2)) * 544 + (uint32_t)(l & 3) * 8;
    const uint32_t lmrow = ((uint32_t)wrow + (uint32_t)(l & 15)) * 272 + (uint32_t)(l >> 4) * 16;

    // ---- ch0: Wp[k<128] x Xh0 ----
    CP_WAIT(1);            // g0 (Xh0 + Wp0) complete
    __syncthreads();       // barrier #1
    gemm_chunk_f32(sb + SM_A0 + f32row, sb + SM_W0, nh, l, acc);
    __syncthreads();       // barrier #2: all W0buf/A0 ch0 reads done

    // prefetch W1 -> W0buf (g2), overlapped with ch1
    {
        const uint4* ws = (const uint4*)(g_wpack + 2 * 8192);
        for (int i = tid; i < 2048; i += 256) CP16(sb + SM_W0 + i * 16, ws + i);
        CP_COMMIT();
    }

    // ---- ch1: Wp[k>=128] x Xh1 (accumulate), then epi1 ----
    CP_WAIT(2);            // g1 (Xh1 + Wp1) complete; g2 in flight
    gemm_chunk_f32(sb + SM_A1 + f32row, sb + SM_W1B, nh, l, acc);

    // epi1: H1 = acc + bp -> A0 (fp16@272). A0's ch0 readers all passed barrier #2.
    {
        const uint32_t bo = sb + SM_BIAS + (uint32_t)nh * 256;
        #pragma unroll
        for (int nb = 0; nb < 8; ++nb) {
            float bx, by;
            lds64f(bo + (uint32_t)(nb * 8 + (l & 3) * 2) * 4, bx, by);
            #pragma unroll
            for (int mb = 0; mb < 2; ++mb) {
                float v0 = acc[mb][nb][0] + bx, v1 = acc[mb][nb][1] + by;
                float v2 = acc[mb][nb][2] + bx, v3 = acc[mb][nb][3] + by;
                uint32_t sa = sb + SM_A0 + (uint32_t)(wrow + mb * 16 + (l >> 2)) * 272
                                         + (uint32_t)(nh * 64 + nb * 8 + (l & 3) * 2) * 2;
                sts32u(sa, packh2(v0, v1));
                sts32u(sa + 8 * 272, packh2(v2, v3));
                acc[mb][nb][0] = 0.f; acc[mb][nb][1] = 0.f;
                acc[mb][nb][2] = 0.f; acc[mb][nb][3] = 0.f;
            }
        }
    }
    __syncthreads();       // barrier #3: H1 visible; W1buf ch1 reads done

    // prefetch W2 -> W1buf (g3), overlapped with ch2
    {
        const uint4* ws = (const uint4*)(g_wpack + 3 * 8192);
        for (int i = tid; i < 2048; i += 256) CP16(sb + SM_W1B + i * 16, ws + i);
        CP_COMMIT();
    }

    // ---- ch2: W1 x H1, then epi2 ----
    CP_WAIT(1);            // g2 (W1) complete; g3 in flight
    gemm_chunk_h16(sb + SM_A0 + lmrow, sb + SM_W0, nh, l, acc);

    // epi2: H2 = relu(acc + b1) -> A1 (fp16@272). A1's ch1 readers passed barrier #3.
    {
        const uint32_t bo = sb + SM_BIAS + 512 + (uint32_t)nh * 256;
        #pragma unroll
        for (int nb = 0; nb < 8; ++nb) {
            float bx, by;
            lds64f(bo + (uint32_t)(nb * 8 + (l & 3) * 2) * 4, bx, by);
            #pragma unroll
            for (int mb = 0; mb < 2; ++mb) {
                float v0 = fmaxf(acc[mb][nb][0] + bx, 0.f);
                float v1 = fmaxf(acc[mb][nb][1] + by, 0.f);
                float v2 = fmaxf(acc[mb][nb][2] + bx, 0.f);
                float v3 = fmaxf(acc[mb][nb][3] + by, 0.f);
                uint32_t sa = sb + SM_A1 + (uint32_t)(wrow + mb * 16 + (l >> 2)) * 272
                                         + (uint32_t)(nh * 64 + nb * 8 + (l & 3) * 2) * 2;
                sts32u(sa, packh2(v0, v1));
                sts32u(sa + 8 * 272, packh2(v2, v3));
                acc[mb][nb][0] = 0.f; acc[mb][nb][1] = 0.f;
                acc[mb][nb][2] = 0.f; acc[mb][nb][3] = 0.f;
            }
        }
    }
    // pair barrier: warp pair (rowgroup) exchanges its H2 rows (both n-halves)
    BAR64(1 + (w >> 1));

    // ---- ch3: W2 x H2, then final epilogue ----
    CP_WAIT(0);            // g3 (W2) complete
    gemm_chunk_h16(sb + SM_A1 + lmrow, sb + SM_W1B, nh, l, acc);

    {
        const size_t rb = (size_t)t * 128 + wrow + (l >> 2);
        float cs[8][2];
        #pragma unroll
        for (int nb = 0; nb < 8; ++nb) { cs[nb][0] = 0.f; cs[nb][1] = 0.f; }
        #pragma unroll
        for (int nb = 0; nb < 8; ++nb) {
            float bx, by;
            lds64f(sb + SM_BIAS + 1024 + (uint32_t)(nh * 64 + nb * 8 + (l & 3) * 2) * 4, bx, by);
            #pragma unroll
            for (int mb = 0; mb < 2; ++mb) {
                float v0 = acc[mb][nb][0] + bx, v1 = acc[mb][nb][1] + by;
                float v2 = acc[mb][nb][2] + bx, v3 = acc[mb][nb][3] + by;
                size_t r0 = (rb + mb * 16) * 128 + nh * 64 + nb * 8 + (l & 3) * 2;
                *(float2*)(out + r0)           = make_float2(v0, v1);
                *(float2*)(out + r0 + 8 * 128) = make_float2(v2, v3);
                cs[nb][0] += v0 + v2;
                cs[nb][1] += v1 + v3;
            }
        }
        #pragma unroll
        for (int nb = 0; nb < 8; ++nb) {
            #pragma unroll
            for (int j = 0; j < 2; ++j) {
                float s = cs[nb][j];
                s += __shfl_down_sync(0xFFFFFFFFu, s, 16);
                s += __shfl_down_sync(0xFFFFFFFFu, s, 8);
                s += __shfl_down_sync(0xFFFFFFFFu, s, 4);
                if (l < 4)
                    ((float*)(smem + SM_RED))[(w >> 1) * 128 + nh * 64 + nb * 8 + l * 2 + j] = s;
            }
        }
    }
    __syncthreads();

    if (tid < 128) {
        const float* R = (const float*)(smem + SM_RED);
        g_part[(size_t)t * 128 + tid] = R[tid] + R[128 + tid] + R[256 + tid] + R[384 + tid];
    }
}

// ---------------- out = S - Y (in place, float4) ----------------
__global__ void subtract_kernel(float* __restrict__ out) {
    __shared__ float4 S4[32];
    int b = blockIdx.x, nc = blockIdx.y, tid = threadIdx.x;
    if (tid < 128) {
        float s = 0.f;
        const float* gp = g_part + (size_t)b * 32 * 128 + tid;
        #pragma unroll
        for (int c = 0; c < 32; ++c) s += gp[c * 128];
        ((float*)S4)[tid] = s;
    }
    __syncthreads();
    float4* p = (float4*)(out + ((size_t)b * 4096 + (size_t)nc * 128) * 128);
    for (int i = tid; i < 4096; i += 256) {
        float4 s = S4[i & 31];
        float4 v = p[i];
        p[i] = make_float4(s.x - v.x, s.y - v.y, s.z - v.z, s.w - v.w);
    }
}

// ---------------- launch ----------------
extern "C" void kernel_launch(void* const* d_in, const int* in_sizes, int n_in,
                              void* d_out, int out_size) {
    const float* X  = (const float*)d_in[0];
    const float* Wp = (const float*)d_in[1];
    const float* bp = (const float*)d_in[2];
    const float* W1 = (const float*)d_in[3];
    const float* b1 = (const float*)d_in[4];
    const float* W2 = (const float*)d_in[5];
    const float* b2 = (const float*)d_in[6];
    float* out = (float*)d_out;

    cudaFuncSetAttribute(fused_kernel,
                         cudaFuncAttributeMaxDynamicSharedMemorySize, SMEM_SZ);

    prep_kernel<<<128, 256>>>(Wp, W1, W2);
    fused_kernel<<<512, 256, SMEM_SZ>>>(X, bp, b1, b2, out);
    subtract_kernel<<<dim3(16, 32), 256>>>(out);
}